// round 15
// baseline (speedup 1.0000x reference)
#include <cuda_runtime.h>
#include <cuda_bf16.h>
#include <math.h>
#include <stdint.h>
#include <string.h>

#define TT 2048
#define DM 2048
#define NH 16
#define HD 128
#define DQKV 6144
#define KSK 512
#define CLIPV 8.0f
#define LNEPS 1e-5f
#define WCAEPS 1e-6f

// ---------------- scratch (device globals; no allocation allowed) ----------
__device__ __align__(128) float g_qkv[(size_t)TT * DQKV];
__device__ __align__(128) float g_krec[(size_t)TT * DM];
__device__ int g_insk[TT];
// bf16 hi/lo operand copies (GEMMs)
__device__ __align__(128) __nv_bfloat16 g_hs_h[(size_t)TT * DM];
__device__ __align__(128) __nv_bfloat16 g_hs_l[(size_t)TT * DM];
__device__ __align__(128) __nv_bfloat16 g_w1_h[(size_t)DQKV * DM];
__device__ __align__(128) __nv_bfloat16 g_w1_l[(size_t)DQKV * DM];
__device__ __align__(128) __nv_bfloat16 g_ow_h[(size_t)DM * DM];
__device__ __align__(128) __nv_bfloat16 g_ow_l[(size_t)DM * DM];
__device__ __align__(128) __nv_bfloat16 g_at_h[(size_t)TT * DM];
__device__ __align__(128) __nv_bfloat16 g_at_l[(size_t)TT * DM];
// bf16 hi/lo attention operands
__device__ __align__(128) __nv_bfloat16 g_qh[(size_t)TT * DM];
__device__ __align__(128) __nv_bfloat16 g_ql[(size_t)TT * DM];
__device__ __align__(128) __nv_bfloat16 g_kh[(size_t)TT * DM];
__device__ __align__(128) __nv_bfloat16 g_kl[(size_t)TT * DM];
__device__ __align__(128) __nv_bfloat16 g_vh[(size_t)TT * DM];
__device__ __align__(128) __nv_bfloat16 g_vl[(size_t)TT * DM];

// ---------------- helpers ----------------------------------------------------
__device__ __forceinline__ uint32_t smem_u32(const void* p) {
    uint32_t a;
    asm("{ .reg .u64 t; cvta.to.shared.u64 t, %1; cvt.u32.u64 %0, t; }"
        : "=r"(a) : "l"(p));
    return a;
}
__device__ __forceinline__ uint32_t swz(uint32_t off) {
    return off ^ ((off >> 3) & 0x70);
}
__device__ __forceinline__ void cp16(uint32_t saddr, const void* gaddr) {
    asm volatile("cp.async.cg.shared.global [%0], [%1], 16;"
                 :: "r"(saddr), "l"(gaddr) : "memory");
}
__device__ __forceinline__ void ldmx4(uint32_t* d, uint32_t addr) {
    asm volatile("ldmatrix.sync.aligned.m8n8.x4.shared.b16 {%0,%1,%2,%3}, [%4];"
                 : "=r"(d[0]), "=r"(d[1]), "=r"(d[2]), "=r"(d[3]) : "r"(addr));
}
__device__ __forceinline__ void ldmx4t(uint32_t* d, uint32_t addr) {
    asm volatile("ldmatrix.sync.aligned.m8n8.x4.trans.shared.b16 {%0,%1,%2,%3}, [%4];"
                 : "=r"(d[0]), "=r"(d[1]), "=r"(d[2]), "=r"(d[3]) : "r"(addr));
}
__device__ __forceinline__ void mma16816(float* c, const uint32_t* a,
                                         uint32_t b0, uint32_t b1) {
    asm volatile("mma.sync.aligned.m16n8k16.row.col.f32.bf16.bf16.f32 "
                 "{%0,%1,%2,%3}, {%4,%5,%6,%7}, {%8,%9}, {%0,%1,%2,%3};"
                 : "+f"(c[0]), "+f"(c[1]), "+f"(c[2]), "+f"(c[3])
                 : "r"(a[0]), "r"(a[1]), "r"(a[2]), "r"(a[3]),
                   "r"(b0), "r"(b1));
}
__device__ __forceinline__ uint32_t pk_bf2(float a, float b) {
    __nv_bfloat162 v = __floats2bfloat162_rn(a, b);
    uint32_t r; memcpy(&r, &v, 4);
    return r;
}
__device__ __forceinline__ void hilo(float x, __nv_bfloat16& h, __nv_bfloat16& l) {
    h = __float2bfloat16_rn(x);
    l = __float2bfloat16_rn(x - __bfloat162float(h));
}

// ---------------- fp32 -> bf16 hi/lo split (MLP=4: 16 floats/thread) ---------
__global__ __launch_bounds__(256) void split_kernel(
    const float* __restrict__ src,
    __nv_bfloat16* __restrict__ hi, __nv_bfloat16* __restrict__ lo)
{
    const size_t i = ((size_t)blockIdx.x * 256 + threadIdx.x) * 16;
    float4 f0 = *(const float4*)(src + i);
    float4 f1 = *(const float4*)(src + i + 4);
    float4 f2 = *(const float4*)(src + i + 8);
    float4 f3 = *(const float4*)(src + i + 12);
    float fv[16] = {f0.x, f0.y, f0.z, f0.w, f1.x, f1.y, f1.z, f1.w,
                    f2.x, f2.y, f2.z, f2.w, f3.x, f3.y, f3.z, f3.w};
    uint32_t hv[8], lv[8];
#pragma unroll
    for (int j = 0; j < 8; j++) {
        __nv_bfloat16 h0, h1, l0, l1;
        hilo(fv[2 * j], h0, l0);
        hilo(fv[2 * j + 1], h1, l1);
        __nv_bfloat162 hh = __halves2bfloat162(h0, h1);
        __nv_bfloat162 ll = __halves2bfloat162(l0, l1);
        memcpy(&hv[j], &hh, 4);
        memcpy(&lv[j], &ll, 4);
    }
    *(uint4*)(hi + i)     = make_uint4(hv[0], hv[1], hv[2], hv[3]);
    *(uint4*)(hi + i + 8) = make_uint4(hv[4], hv[5], hv[6], hv[7]);
    *(uint4*)(lo + i)     = make_uint4(lv[0], lv[1], lv[2], lv[3]);
    *(uint4*)(lo + i + 8) = make_uint4(lv[4], lv[5], lv[6], lv[7]);
}

// ================= HMMA split-bf16 GEMM, shared-operand, PASS-MAJOR ==========
// 256 threads (8 warps, 4x2), block 256x128, warp tile 64x64, BK=64,
// 2-stage 96KB pipeline. Per ks-step: 3 pass-major MMA sweeps (Ah*Bh, Al*Bh,
// Ah*Bl) of 32 independent MMAs each -> accumulator RAW reuse separated by 31
// independent MMAs (kills the 67% dependent-triple ceiling).
#define GK 2048
#define GBK 64
#define NCH 32
#define A_BYTES  32768                 // 256 rows x 128B
#define B_BYTES  16384                 // 128 rows x 128B
#define STAGE (2 * A_BYTES + 2 * B_BYTES)   // 98304
#define GSM_BYTES (2 * STAGE)               // 196608

__global__ __launch_bounds__(256, 1) void gemm_mma(
    const __nv_bfloat16* __restrict__ Ah, const __nv_bfloat16* __restrict__ Al,
    const __nv_bfloat16* __restrict__ Bh, const __nv_bfloat16* __restrict__ Bl,
    float* __restrict__ C, int ldc, int doClip)
{
    extern __shared__ __align__(1024) char smem[];
    const uint32_t smem_base = smem_u32(smem);
    const int tid = threadIdx.x;
    const int wid = tid >> 5;
    const int lane = tid & 31;
    const int bm = blockIdx.y * 256;
    const int bn = blockIdx.x * 128;
    const int wm = (wid >> 1) * 64;
    const int wn = (wid & 1) * 64;

    const uint32_t lq = lane >> 3, lr = lane & 7;
    const int aRow = wm + (lq & 1) * 8 + lr;
    const int aCol = (lq >> 1) * 16;
    const int bRow = wn + (lq >> 1) * 8 + lr;
    const int bCol = (lq & 1) * 16;

    float acc[4][8][4];
#pragma unroll
    for (int i = 0; i < 4; i++)
#pragma unroll
        for (int j = 0; j < 8; j++)
#pragma unroll
            for (int k = 0; k < 4; k++) acc[i][j][k] = 0.f;

    auto prefetch = [&](int c, int b) {
        const int kk = c * GBK;
        const uint32_t base = smem_base + b * STAGE;
        const uint32_t sAh = base;
        const uint32_t sAl = base + A_BYTES;
        const uint32_t sBh = base + 2 * A_BYTES;
        const uint32_t sBl = sBh + B_BYTES;
#pragma unroll
        for (int i = 0; i < 8; i++) {
            const int idx = tid + i * 256;
            const int row = idx >> 3, c16 = idx & 7;
            const uint32_t off = swz(row * 128 + c16 * 16);
            const size_t go = (size_t)(bm + row) * GK + kk + c16 * 8;
            cp16(sAh + off, Ah + go);
            cp16(sAl + off, Al + go);
        }
#pragma unroll
        for (int i = 0; i < 4; i++) {
            const int idx = tid + i * 256;
            const int row = idx >> 3, c16 = idx & 7;
            const uint32_t off = swz(row * 128 + c16 * 16);
            const size_t go = (size_t)(bn + row) * GK + kk + c16 * 8;
            cp16(sBh + off, Bh + go);
            cp16(sBl + off, Bl + go);
        }
        asm volatile("cp.async.commit_group;" ::: "memory");
    };

    prefetch(0, 0);
    prefetch(1, 1);

    for (int c = 0; c < NCH; c++) {
        const int b = c & 1;
        if (c == NCH - 1) asm volatile("cp.async.wait_group 0;" ::: "memory");
        else              asm volatile("cp.async.wait_group 1;" ::: "memory");
        __syncthreads();

        const uint32_t base = smem_base + b * STAGE;
        const uint32_t sAh = base;
        const uint32_t sAl = base + A_BYTES;
        const uint32_t sBh = base + 2 * A_BYTES;
        const uint32_t sBl = sBh + B_BYTES;
#pragma unroll
        for (int ks = 0; ks < 4; ks++) {
            uint32_t Afh[4][4], Afl[4][4], Bfh[4][4], Bfl[4][4];
#pragma unroll
            for (int mt = 0; mt < 4; mt++) {
                const uint32_t ao = swz((aRow + mt * 16) * 128 + aCol + ks * 32);
                ldmx4(Afh[mt], sAh + ao);
                ldmx4(Afl[mt], sAl + ao);
            }
#pragma unroll
            for (int nt2 = 0; nt2 < 4; nt2++) {
                const uint32_t bo = swz((bRow + nt2 * 16) * 128 + bCol + ks * 32);
                ldmx4(Bfh[nt2], sBh + bo);
                ldmx4(Bfl[nt2], sBl + bo);
            }
            // pass 0: Ah * Bh  (32 independent MMAs)
#pragma unroll
            for (int mt = 0; mt < 4; mt++)
#pragma unroll
                for (int nt = 0; nt < 8; nt++)
                    mma16816(acc[mt][nt], Afh[mt],
                             Bfh[nt >> 1][(nt & 1) * 2],
                             Bfh[nt >> 1][(nt & 1) * 2 + 1]);
            // pass 1: Al * Bh
#pragma unroll
            for (int mt = 0; mt < 4; mt++)
#pragma unroll
                for (int nt = 0; nt < 8; nt++)
                    mma16816(acc[mt][nt], Afl[mt],
                             Bfh[nt >> 1][(nt & 1) * 2],
                             Bfh[nt >> 1][(nt & 1) * 2 + 1]);
            // pass 2: Ah * Bl
#pragma unroll
            for (int mt = 0; mt < 4; mt++)
#pragma unroll
                for (int nt = 0; nt < 8; nt++)
                    mma16816(acc[mt][nt], Afh[mt],
                             Bfl[nt >> 1][(nt & 1) * 2],
                             Bfl[nt >> 1][(nt & 1) * 2 + 1]);
        }
        __syncthreads();
        if (c + 2 < NCH) prefetch(c + 2, b);
    }

    const int erow = (int)(lane >> 2);
    const int ecol = (int)(lane & 3) * 2;
#pragma unroll
    for (int mt = 0; mt < 4; mt++) {
#pragma unroll
        for (int nt = 0; nt < 8; nt++) {
            const int row0 = bm + wm + mt * 16 + erow;
            const int col  = bn + wn + nt * 8 + ecol;
            float2 v0 = make_float2(acc[mt][nt][0], acc[mt][nt][1]);
            float2 v1 = make_float2(acc[mt][nt][2], acc[mt][nt][3]);
            if (doClip) {
                v0.x = fminf(fmaxf(v0.x, -CLIPV), CLIPV);
                v0.y = fminf(fmaxf(v0.y, -CLIPV), CLIPV);
                v1.x = fminf(fmaxf(v1.x, -CLIPV), CLIPV);
                v1.y = fminf(fmaxf(v1.y, -CLIPV), CLIPV);
            }
            *(float2*)(C + (size_t)row0 * ldc + col) = v0;
            *(float2*)(C + (size_t)(row0 + 8) * ldc + col) = v1;
        }
    }
}

// ---------------- LayerNorm -> fp32 (for krec) -------------------------------
__global__ __launch_bounds__(256) void ln_kernel(
    const float* __restrict__ src, const float* __restrict__ w,
    const float* __restrict__ b, float* __restrict__ dst)
{
    __shared__ float r1[256], r2[256];
    const int row = blockIdx.x;
    const int tid = threadIdx.x;
    const float* x = src + (size_t)row * DQKV;
    float xv[8];
    float s = 0.f, ss = 0.f;
#pragma unroll
    for (int i = 0; i < 8; i++) {
        xv[i] = x[i * 256 + tid];
        s += xv[i];
        ss += xv[i] * xv[i];
    }
    r1[tid] = s; r2[tid] = ss;
    __syncthreads();
    for (int off = 128; off > 0; off >>= 1) {
        if (tid < off) { r1[tid] += r1[tid + off]; r2[tid] += r2[tid + off]; }
        __syncthreads();
    }
    const float mu  = r1[0] * (1.f / DM);
    const float var = r2[0] * (1.f / DM) - mu * mu;
    const float rs  = rsqrtf(var + LNEPS);
#pragma unroll
    for (int i = 0; i < 8; i++) {
        const int d = i * 256 + tid;
        dst[(size_t)row * DM + d] = (xv[i] - mu) * rs * w[d] + b[d];
    }
}

// ---------------- LayerNorm -> bf16 hi/lo (for q) ----------------------------
__global__ __launch_bounds__(256) void ln_bf16_kernel(
    const float* __restrict__ src, const float* __restrict__ w,
    const float* __restrict__ b,
    __nv_bfloat16* __restrict__ hi, __nv_bfloat16* __restrict__ lo)
{
    __shared__ float r1[256], r2[256];
    const int row = blockIdx.x;
    const int tid = threadIdx.x;
    const float* x = src + (size_t)row * DQKV;
    float xv[8];
    float s = 0.f, ss = 0.f;
#pragma unroll
    for (int i = 0; i < 8; i++) {
        xv[i] = x[i * 256 + tid];
        s += xv[i];
        ss += xv[i] * xv[i];
    }
    r1[tid] = s; r2[tid] = ss;
    __syncthreads();
    for (int off = 128; off > 0; off >>= 1) {
        if (tid < off) { r1[tid] += r1[tid + off]; r2[tid] += r2[tid + off]; }
        __syncthreads();
    }
    const float mu  = r1[0] * (1.f / DM);
    const float var = r2[0] * (1.f / DM) - mu * mu;
    const float rs  = rsqrtf(var + LNEPS);
#pragma unroll
    for (int i = 0; i < 8; i++) {
        const int d = i * 256 + tid;
        const float y = (xv[i] - mu) * rs * w[d] + b[d];
        __nv_bfloat16 h, l;
        hilo(y, h, l);
        hi[(size_t)row * DM + d] = h;
        lo[(size_t)row * DM + d] = l;
    }
}

// ---------------- Sk mask ------------------------------------------------------
__global__ void mask_zero_kernel() {
    g_insk[blockIdx.x * 256 + threadIdx.x] = 0;
}
__global__ void mask_set_kernel(const int* __restrict__ Sk) {
    g_insk[Sk[blockIdx.x * 256 + threadIdx.x]] = 1;
}

// ---------------- fused gather + blend + bf16 split for K/V -------------------
__global__ __launch_bounds__(256) void kv_fuse(
    const float* __restrict__ kc, const float* __restrict__ vc,
    const int* __restrict__ cidx)
{
    __shared__ float r1[256], r2[256];
    __shared__ float s_alpha;
    const int t = blockIdx.x;
    const int tid = threadIdx.x;
    const int ci = cidx[t];
    const bool reuse = (ci >= 0);
    const int ci0 = reuse ? ci : 0;
    const bool doBlend = (g_insk[t] != 0);
    const float* krec = g_krec + (size_t)t * DM;
    const float* vrec = g_qkv + (size_t)t * DQKV + 2 * DM;
    const float* kr   = kc + (size_t)ci0 * DM;
    const float* vr   = vc + (size_t)ci0 * DM;

    float kv[8], vv[8];
    if (doBlend) {
        float krv[8], krecv[8];
        float num = 0.f, den = 0.f;
#pragma unroll
        for (int i = 0; i < 8; i++) {
            const int d = i * 256 + tid;
            krv[i] = kr[d]; krecv[i] = krec[d];
            const float df = krecv[i] - krv[i];
            num += df * df;
            den += krv[i] * krv[i];
        }
        r1[tid] = num; r2[tid] = den;
        __syncthreads();
        for (int off = 128; off > 0; off >>= 1) {
            if (tid < off) { r1[tid] += r1[tid + off]; r2[tid] += r2[tid + off]; }
            __syncthreads();
        }
        if (tid == 0) {
            float a = r1[0] / fmaxf(r2[0], WCAEPS);
            s_alpha = fminf(fmaxf(a, 0.f), 1.f);
        }
        __syncthreads();
        const float alpha = s_alpha;
#pragma unroll
        for (int i = 0; i < 8; i++) {
            const int d = i * 256 + tid;
            kv[i] = alpha * krecv[i] + (1.f - alpha) * krv[i];
            vv[i] = alpha * vrec[d]  + (1.f - alpha) * vr[d];
        }
    } else if (reuse) {
#pragma unroll
        for (int i = 0; i < 8; i++) {
            const int d = i * 256 + tid;
            kv[i] = kr[d]; vv[i] = vr[d];
        }
    } else {
#pragma unroll
        for (int i = 0; i < 8; i++) {
            const int d = i * 256 + tid;
            kv[i] = krec[d]; vv[i] = vrec[d];
        }
    }
#pragma unroll
    for (int i = 0; i < 8; i++) {
        const size_t d = (size_t)t * DM + i * 256 + tid;
        __nv_bfloat16 h, l;
        hilo(kv[i], h, l);
        g_kh[d] = h; g_kl[d] = l;
        hilo(vv[i], h, l);
        g_vh[d] = h; g_vl[d] = l;
    }
}

// ---------------- FlashAttention-2 on mma.sync, split-bf16 -------------------
#define STR 272
#define QSM (2 * 128 * STR)
#define KVSM (4 * 64 * STR)
#define ATT_SMEM (QSM + 2 * KVSM)

__global__ __launch_bounds__(256, 1) void attn_mma()
{
    extern __shared__ __align__(1024) char asmem[];
    const uint32_t sb = smem_u32(asmem);
    const int tid = threadIdx.x;
    const int wid = tid >> 5, ln = tid & 31;
    const int h = blockIdx.y;
    const int qt = (int)(gridDim.x - 1 - blockIdx.x);
    const int t0 = qt * 128;
    const int m0 = wid * 16;
    const int g = ln >> 2, qd = ln & 3;
    const int lq = ln >> 3, lr = ln & 7;
    const float slope = exp2f(-0.5f * (float)(h + 1));
    const float scl = 0.08838834764831845f;
    const int lastj = 2 * qt + 1;

    const uint32_t sQh = sb, sQl = sb + 128 * STR;

    {
        const __nv_bfloat16* S0 = g_qh + (size_t)t0 * DM + h * HD;
        const __nv_bfloat16* S1 = g_ql + (size_t)t0 * DM + h * HD;
#pragma unroll
        for (int i = 0; i < 8; i++) {
            const int idx = tid + i * 256;
            const int row = idx >> 4, c = idx & 15;
            cp16(sQh + row * STR + c * 16, S0 + (size_t)row * DM + c * 8);
            cp16(sQl + row * STR + c * 16, S1 + (size_t)row * DM + c * 8);
        }
        asm volatile("cp.async.commit_group;" ::: "memory");
    }

    auto loadKV = [&](int jt, int s) {
        const int j0 = jt * 64;
        const uint32_t base = sb + QSM + s * KVSM;
        const size_t goff = (size_t)j0 * DM + h * HD;
        const __nv_bfloat16* P0 = g_kh + goff;
        const __nv_bfloat16* P1 = g_kl + goff;
        const __nv_bfloat16* P2 = g_vh + goff;
        const __nv_bfloat16* P3 = g_vl + goff;
#pragma unroll
        for (int i = 0; i < 4; i++) {
            const int idx = tid + i * 256;
            const int row = idx >> 4, c = idx & 15;
            const uint32_t d = base + row * STR + c * 16;
            const size_t o = (size_t)row * DM + c * 8;
            cp16(d,             P0 + o);
            cp16(d + 64 * STR,  P1 + o);
            cp16(d + 128 * STR, P2 + o);
            cp16(d + 192 * STR, P3 + o);
        }
        asm volatile("cp.async.commit_group;" ::: "memory");
    };
    loadKV(0, 0);
    loadKV(1, 1);

    const uint32_t aAB = (uint32_t)((m0 + (lq & 1) * 8 + lr) * STR + (lq >> 1) * 16);
    const uint32_t bAB = (uint32_t)(((lq >> 1) * 8 + lr) * STR + (lq & 1) * 16);
    const uint32_t vAB = (uint32_t)(((lq & 1) * 8 + lr) * STR + (lq >> 1) * 16);

    float accO[16][4];
#pragma unroll
    for (int i = 0; i < 16; i++)
#pragma unroll
        for (int j = 0; j < 4; j++) accO[i][j] = 0.f;
    float mS0 = -1e30f, mS1 = -1e30f, lS0 = 0.f, lS1 = 0.f;

    for (int jt = 0; jt <= lastj; jt++) {
        const int s = jt & 1;
        if (jt == lastj) asm volatile("cp.async.wait_group 0;" ::: "memory");
        else             asm volatile("cp.async.wait_group 1;" ::: "memory");
        __syncthreads();
        const uint32_t kh = sb + QSM + s * KVSM;
        const uint32_t kl = kh + 64 * STR;
        const uint32_t vh = kh + 128 * STR;
        const uint32_t vl = kh + 192 * STR;

        float accS[8][4];
#pragma unroll
        for (int i = 0; i < 8; i++)
#pragma unroll
            for (int j = 0; j < 4; j++) accS[i][j] = 0.f;
#pragma unroll
        for (int kc = 0; kc < 8; kc++) {
            uint32_t aQh[4], aQl[4];
            ldmx4(aQh, sQh + aAB + kc * 32);
            ldmx4(aQl, sQl + aAB + kc * 32);
#pragma unroll
            for (int ntp = 0; ntp < 4; ntp++) {
                uint32_t bKh[4], bKl[4];
                ldmx4(bKh, kh + bAB + ntp * (16 * STR) + kc * 32);
                ldmx4(bKl, kl + bAB + ntp * (16 * STR) + kc * 32);
                mma16816(accS[2 * ntp],     aQh, bKh[0], bKh[1]);
                mma16816(accS[2 * ntp + 1], aQh, bKh[2], bKh[3]);
                mma16816(accS[2 * ntp],     aQl, bKh[0], bKh[1]);
                mma16816(accS[2 * ntp + 1], aQl, bKh[2], bKh[3]);
                mma16816(accS[2 * ntp],     aQh, bKl[0], bKl[1]);
                mma16816(accS[2 * ntp + 1], aQh, bKl[2], bKl[3]);
            }
        }

        const int j0 = jt * 64;
        const int qi0 = t0 + m0 + g;
        const int qi1 = qi0 + 8;
        float mx0 = -1e30f, mx1 = -1e30f;
#pragma unroll
        for (int nt = 0; nt < 8; nt++) {
            const int kj = j0 + nt * 8 + qd * 2;
            float s0 = accS[nt][0] * scl + slope * (float)(kj - qi0);
            float s1 = accS[nt][1] * scl + slope * (float)(kj + 1 - qi0);
            float s2 = accS[nt][2] * scl + slope * (float)(kj - qi1);
            float s3 = accS[nt][3] * scl + slope * (float)(kj + 1 - qi1);
            if (kj > qi0)     s0 = -1e30f;
            if (kj + 1 > qi0) s1 = -1e30f;
            if (kj > qi1)     s2 = -1e30f;
            if (kj + 1 > qi1) s3 = -1e30f;
            accS[nt][0] = s0; accS[nt][1] = s1; accS[nt][2] = s2; accS[nt][3] = s3;
            mx0 = fmaxf(mx0, fmaxf(s0, s1));
            mx1 = fmaxf(mx1, fmaxf(s2, s3));
        }
        mx0 = fmaxf(mx0, __shfl_xor_sync(0xffffffffu, mx0, 1));
        mx0 = fmaxf(mx0, __shfl_xor_sync(0xffffffffu, mx0, 2));
        mx1 = fmaxf(mx1, __shfl_xor_sync(0xffffffffu, mx1, 1));
        mx1 = fmaxf(mx1, __shfl_xor_sync(0xffffffffu, mx1, 2));
        const float mN0 = fmaxf(mS0, mx0), mN1 = fmaxf(mS1, mx1);
        const float sc0 = __expf(mS0 - mN0), sc1 = __expf(mS1 - mN1);
        float sum0 = 0.f, sum1 = 0.f;
#pragma unroll
        for (int nt = 0; nt < 8; nt++) {
            accS[nt][0] = __expf(accS[nt][0] - mN0);
            accS[nt][1] = __expf(accS[nt][1] - mN0);
            accS[nt][2] = __expf(accS[nt][2] - mN1);
            accS[nt][3] = __expf(accS[nt][3] - mN1);
            sum0 += accS[nt][0] + accS[nt][1];
            sum1 += accS[nt][2] + accS[nt][3];
        }
        sum0 += __shfl_xor_sync(0xffffffffu, sum0, 1);
        sum0 += __shfl_xor_sync(0xffffffffu, sum0, 2);
        sum1 += __shfl_xor_sync(0xffffffffu, sum1, 1);
        sum1 += __shfl_xor_sync(0xffffffffu, sum1, 2);
        lS0 = lS0 * sc0 + sum0;
        lS1 = lS1 * sc1 + sum1;
        mS0 = mN0; mS1 = mN1;
#pragma unroll
        for (int nt = 0; nt < 16; nt++) {
            accO[nt][0] *= sc0; accO[nt][1] *= sc0;
            accO[nt][2] *= sc1; accO[nt][3] *= sc1;
        }

        uint32_t aPh[4][4], aPl[4][4];
#pragma unroll
        for (int kc = 0; kc < 4; kc++) {
#pragma unroll
            for (int e = 0; e < 4; e++) {
                const int nt = 2 * kc + (e >> 1);
                const int b0 = (e & 1) * 2;
                const float p0 = accS[nt][b0], p1 = accS[nt][b0 + 1];
                const __nv_bfloat16 h0 = __float2bfloat16_rn(p0);
                const __nv_bfloat16 h1 = __float2bfloat16_rn(p1);
                __nv_bfloat162 hh = __halves2bfloat162(h0, h1);
                memcpy(&aPh[kc][e], &hh, 4);
                aPl[kc][e] = pk_bf2(p0 - __bfloat162float(h0),
                                    p1 - __bfloat162float(h1));
            }
        }

#pragma unroll
        for (int ntp = 0; ntp < 8; ntp++) {
#pragma unroll
            for (int kc = 0; kc < 4; kc++) {
                uint32_t bVh[4], bVl[4];
                ldmx4t(bVh, vh + vAB + kc * (16 * STR) + ntp * 32);
                ldmx4t(bVl, vl + vAB + kc * (16 * STR) + ntp * 32);
                mma16816(accO[2 * ntp],     aPh[kc], bVh[0], bVh[1]);
                mma16816(accO[2 * ntp + 1], aPh[kc], bVh[2], bVh[3]);
                mma16816(accO[2 * ntp],     aPl[kc], bVh[0], bVh[1]);
                mma16816(accO[2 * ntp + 1], aPl[kc], bVh[2], bVh[3]);
                mma16816(accO[2 * ntp],     aPh[kc], bVl[0], bVl[1]);
                mma16816(accO[2 * ntp + 1], aPh[kc], bVl[2], bVl[3]);
            }
        }
        __syncthreads();
        if (jt + 2 <= lastj) loadKV(jt + 2, s);
    }

    // ---- epilogue: write bf16 hi/lo directly (feeds gemm2) ----
    const float i0 = 1.f / lS0, i1 = 1.f / lS1;
    const size_t base0 = (size_t)(t0 + m0 + g) * DM + h * HD + qd * 2;
    const size_t base1 = base0 + (size_t)8 * DM;
#pragma unroll
    for (int nt = 0; nt < 16; nt++) {
        float a0 = accO[nt][0] * i0, a1 = accO[nt][1] * i0;
        float a2 = accO[nt][2] * i1, a3 = accO[nt][3] * i1;
        __nv_bfloat16 h0, h1, h2, h3, l0, l1, l2, l3;
        hilo(a0, h0, l0); hilo(a1, h1, l1);
        hilo(a2, h2, l2); hilo(a3, h3, l3);
        *(__nv_bfloat162*)(g_at_h + base0 + nt * 8) = __halves2bfloat162(h0, h1);
        *(__nv_bfloat162*)(g_at_l + base0 + nt * 8) = __halves2bfloat162(l0, l1);
        *(__nv_bfloat162*)(g_at_h + base1 + nt * 8) = __halves2bfloat162(h2, h3);
        *(__nv_bfloat162*)(g_at_l + base1 + nt * 8) = __halves2bfloat162(l2, l3);
    }
}

// ---------------- launch ------------------------------------------------------
extern "C" void kernel_launch(void* const* d_in, const int* in_sizes, int n_in,
                              void* d_out, int out_size)
{
    const float* hs   = (const float*)d_in[0];
    const float* Wqkv = (const float*)d_in[1];
    const float* qw   = (const float*)d_in[2];
    const float* qb   = (const float*)d_in[3];
    const float* kw   = (const float*)d_in[4];
    const float* kb   = (const float*)d_in[5];
    const float* outw = (const float*)d_in[6];
    const float* kc   = (const float*)d_in[7];
    const float* vc   = (const float*)d_in[8];
    const int*   cidx = (const int*)d_in[9];
    const int*   Sk   = (const int*)d_in[10];
    float* out = (float*)d_out;

    float *p_qkv, *p_krec;
    cudaGetSymbolAddress((void**)&p_qkv,  g_qkv);
    cudaGetSymbolAddress((void**)&p_krec, g_krec);
    __nv_bfloat16 *hs_h, *hs_l, *w1_h, *w1_l, *ow_h, *ow_l, *at_h, *at_l, *qh_, *ql_;
    cudaGetSymbolAddress((void**)&hs_h, g_hs_h);
    cudaGetSymbolAddress((void**)&hs_l, g_hs_l);
    cudaGetSymbolAddress((void**)&w1_h, g_w1_h);
    cudaGetSymbolAddress((void**)&w1_l, g_w1_l);
    cudaGetSymbolAddress((void**)&ow_h, g_ow_h);
    cudaGetSymbolAddress((void**)&ow_l, g_ow_l);
    cudaGetSymbolAddress((void**)&at_h, g_at_h);
    cudaGetSymbolAddress((void**)&at_l, g_at_l);
    cudaGetSymbolAddress((void**)&qh_, g_qh);
    cudaGetSymbolAddress((void**)&ql_, g_ql);

    cudaFuncSetAttribute(gemm_mma, cudaFuncAttributeMaxDynamicSharedMemorySize,
                         GSM_BYTES);
    cudaFuncSetAttribute(attn_mma, cudaFuncAttributeMaxDynamicSharedMemorySize,
                         ATT_SMEM);

    // 0. bf16 hi/lo splits of GEMM operands (16 floats per thread)
    split_kernel<<<(TT * DM) / 4096, 256>>>(hs, hs_h, hs_l);
    split_kernel<<<((size_t)DQKV * DM) / 4096, 256>>>(Wqkv, w1_h, w1_l);
    split_kernel<<<(DM * DM) / 4096, 256>>>(outw, ow_h, ow_l);
    // 1. QKV projection + clip (block 256x128)
    gemm_mma<<<dim3(DQKV / 128, TT / 256), 256, GSM_BYTES>>>(
        hs_h, hs_l, w1_h, w1_l, p_qkv, DQKV, 1);
    // 2. LayerNorm: q -> bf16 hi/lo directly; k -> fp32 krec
    ln_bf16_kernel<<<TT, 256>>>(p_qkv + 0, qw, qb, qh_, ql_);
    ln_kernel<<<TT, 256>>>(p_qkv + DM, kw, kb, p_krec);
    // 3. Sk mask
    mask_zero_kernel<<<TT / 256, 256>>>();
    mask_set_kernel<<<KSK / 256, 256>>>(Sk);
    // 4. fused gather + blend + split -> kh/kl/vh/vl
    kv_fuse<<<TT, 256>>>(kc, vc, cidx);
    // 5. attention (writes at_h/at_l bf16 hi/lo)
    attn_mma<<<dim3(TT / 128, NH), 256, ATT_SMEM>>>();
    // 6. output projection
    gemm_mma<<<dim3(DM / 128, TT / 256), 256, GSM_BYTES>>>(
        at_h, at_l, ow_h, ow_l, out, DM, 0);
}

// round 16
// speedup vs baseline: 1.0156x; 1.0156x over previous
#include <cuda_runtime.h>
#include <cuda_bf16.h>
#include <math.h>
#include <stdint.h>
#include <string.h>

#define TT 2048
#define DM 2048
#define NH 16
#define HD 128
#define DQKV 6144
#define KSK 512
#define CLIPV 8.0f
#define LNEPS 1e-5f
#define WCAEPS 1e-6f

// ---------------- scratch (device globals; no allocation allowed) ----------
__device__ __align__(128) float g_qkv[(size_t)TT * DQKV];
__device__ int g_insk[TT];
// bf16 hi/lo operand copies (GEMMs)
__device__ __align__(128) __nv_bfloat16 g_hs_h[(size_t)TT * DM];
__device__ __align__(128) __nv_bfloat16 g_hs_l[(size_t)TT * DM];
__device__ __align__(128) __nv_bfloat16 g_w1_h[(size_t)DQKV * DM];
__device__ __align__(128) __nv_bfloat16 g_w1_l[(size_t)DQKV * DM];
__device__ __align__(128) __nv_bfloat16 g_ow_h[(size_t)DM * DM];
__device__ __align__(128) __nv_bfloat16 g_ow_l[(size_t)DM * DM];
__device__ __align__(128) __nv_bfloat16 g_at_h[(size_t)TT * DM];
__device__ __align__(128) __nv_bfloat16 g_at_l[(size_t)TT * DM];
// bf16 hi/lo attention operands
__device__ __align__(128) __nv_bfloat16 g_qh[(size_t)TT * DM];
__device__ __align__(128) __nv_bfloat16 g_ql[(size_t)TT * DM];
__device__ __align__(128) __nv_bfloat16 g_kh[(size_t)TT * DM];
__device__ __align__(128) __nv_bfloat16 g_kl[(size_t)TT * DM];
__device__ __align__(128) __nv_bfloat16 g_vh[(size_t)TT * DM];
__device__ __align__(128) __nv_bfloat16 g_vl[(size_t)TT * DM];

// ---------------- helpers ----------------------------------------------------
__device__ __forceinline__ uint32_t smem_u32(const void* p) {
    uint32_t a;
    asm("{ .reg .u64 t; cvta.to.shared.u64 t, %1; cvt.u32.u64 %0, t; }"
        : "=r"(a) : "l"(p));
    return a;
}
__device__ __forceinline__ uint32_t swz(uint32_t off) {
    return off ^ ((off >> 3) & 0x70);
}
__device__ __forceinline__ void cp16(uint32_t saddr, const void* gaddr) {
    asm volatile("cp.async.cg.shared.global [%0], [%1], 16;"
                 :: "r"(saddr), "l"(gaddr) : "memory");
}
__device__ __forceinline__ void ldmx4(uint32_t* d, uint32_t addr) {
    asm volatile("ldmatrix.sync.aligned.m8n8.x4.shared.b16 {%0,%1,%2,%3}, [%4];"
                 : "=r"(d[0]), "=r"(d[1]), "=r"(d[2]), "=r"(d[3]) : "r"(addr));
}
__device__ __forceinline__ void ldmx4t(uint32_t* d, uint32_t addr) {
    asm volatile("ldmatrix.sync.aligned.m8n8.x4.trans.shared.b16 {%0,%1,%2,%3}, [%4];"
                 : "=r"(d[0]), "=r"(d[1]), "=r"(d[2]), "=r"(d[3]) : "r"(addr));
}
__device__ __forceinline__ void mma16816(float* c, const uint32_t* a,
                                         uint32_t b0, uint32_t b1) {
    asm volatile("mma.sync.aligned.m16n8k16.row.col.f32.bf16.bf16.f32 "
                 "{%0,%1,%2,%3}, {%4,%5,%6,%7}, {%8,%9}, {%0,%1,%2,%3};"
                 : "+f"(c[0]), "+f"(c[1]), "+f"(c[2]), "+f"(c[3])
                 : "r"(a[0]), "r"(a[1]), "r"(a[2]), "r"(a[3]),
                   "r"(b0), "r"(b1));
}
__device__ __forceinline__ uint32_t pk_bf2(float a, float b) {
    __nv_bfloat162 v = __floats2bfloat162_rn(a, b);
    uint32_t r; memcpy(&r, &v, 4);
    return r;
}
__device__ __forceinline__ void hilo(float x, __nv_bfloat16& h, __nv_bfloat16& l) {
    h = __float2bfloat16_rn(x);
    l = __float2bfloat16_rn(x - __bfloat162float(h));
}

// ---------------- fused fp32 -> bf16 hi/lo split (3 tensors, 1 launch) -------
// blocks [0, n0): hs, [n0, n0+n1): w1, rest: ow. 16 floats/thread.
__global__ __launch_bounds__(256) void split3_kernel(
    const float* __restrict__ s0, __nv_bfloat16* __restrict__ h0p,
    __nv_bfloat16* __restrict__ l0p,
    const float* __restrict__ s1, __nv_bfloat16* __restrict__ h1p,
    __nv_bfloat16* __restrict__ l1p,
    const float* __restrict__ s2, __nv_bfloat16* __restrict__ h2p,
    __nv_bfloat16* __restrict__ l2p,
    int n0, int n1)
{
    int b = blockIdx.x;
    const float* src;
    __nv_bfloat16 *hi, *lo;
    if (b < n0)           { src = s0; hi = h0p; lo = l0p; }
    else if (b < n0 + n1) { src = s1; hi = h1p; lo = l1p; b -= n0; }
    else                  { src = s2; hi = h2p; lo = l2p; b -= n0 + n1; }
    const size_t i = ((size_t)b * 256 + threadIdx.x) * 16;
    float4 f0 = *(const float4*)(src + i);
    float4 f1 = *(const float4*)(src + i + 4);
    float4 f2 = *(const float4*)(src + i + 8);
    float4 f3 = *(const float4*)(src + i + 12);
    float fv[16] = {f0.x, f0.y, f0.z, f0.w, f1.x, f1.y, f1.z, f1.w,
                    f2.x, f2.y, f2.z, f2.w, f3.x, f3.y, f3.z, f3.w};
    uint32_t hv[8], lv[8];
#pragma unroll
    for (int j = 0; j < 8; j++) {
        __nv_bfloat16 h0, h1, l0, l1;
        hilo(fv[2 * j], h0, l0);
        hilo(fv[2 * j + 1], h1, l1);
        __nv_bfloat162 hh = __halves2bfloat162(h0, h1);
        __nv_bfloat162 ll = __halves2bfloat162(l0, l1);
        memcpy(&hv[j], &hh, 4);
        memcpy(&lv[j], &ll, 4);
    }
    *(uint4*)(hi + i)     = make_uint4(hv[0], hv[1], hv[2], hv[3]);
    *(uint4*)(hi + i + 8) = make_uint4(hv[4], hv[5], hv[6], hv[7]);
    *(uint4*)(lo + i)     = make_uint4(lv[0], lv[1], lv[2], lv[3]);
    *(uint4*)(lo + i + 8) = make_uint4(lv[4], lv[5], lv[6], lv[7]);
}

// ================= HMMA split-bf16 GEMM, pass-major, NARROW LIVENESS =========
// 256 threads (8 warps, 4x2), block 256x128, warp tile 64x64, BK=64,
// 2-stage 96KB pipeline. Fragments loaded per-pass with a shared reuse buffer
// X (Afl then Bfl) so max live fragments = 48 regs (vs 64) -> kill spills.
#define GK 2048
#define GBK 64
#define NCH 32
#define A_BYTES  32768
#define B_BYTES  16384
#define STAGE (2 * A_BYTES + 2 * B_BYTES)   // 98304
#define GSM_BYTES (2 * STAGE)               // 196608

__global__ __launch_bounds__(256, 1) void gemm_mma(
    const __nv_bfloat16* __restrict__ Ah, const __nv_bfloat16* __restrict__ Al,
    const __nv_bfloat16* __restrict__ Bh, const __nv_bfloat16* __restrict__ Bl,
    float* __restrict__ C, int ldc, int doClip)
{
    extern __shared__ __align__(1024) char smem[];
    const uint32_t smem_base = smem_u32(smem);
    const int tid = threadIdx.x;
    const int wid = tid >> 5;
    const int lane = tid & 31;
    const int bm = blockIdx.y * 256;
    const int bn = blockIdx.x * 128;
    const int wm = (wid >> 1) * 64;
    const int wn = (wid & 1) * 64;

    const uint32_t lq = lane >> 3, lr = lane & 7;
    const int aRow = wm + (lq & 1) * 8 + lr;
    const int aCol = (lq >> 1) * 16;
    const int bRow = wn + (lq >> 1) * 8 + lr;
    const int bCol = (lq & 1) * 16;

    float acc[4][8][4];
#pragma unroll
    for (int i = 0; i < 4; i++)
#pragma unroll
        for (int j = 0; j < 8; j++)
#pragma unroll
            for (int k = 0; k < 4; k++) acc[i][j][k] = 0.f;

    auto prefetch = [&](int c, int b) {
        const int kk = c * GBK;
        const uint32_t base = smem_base + b * STAGE;
        const uint32_t sAh = base;
        const uint32_t sAl = base + A_BYTES;
        const uint32_t sBh = base + 2 * A_BYTES;
        const uint32_t sBl = sBh + B_BYTES;
#pragma unroll
        for (int i = 0; i < 8; i++) {
            const int idx = tid + i * 256;
            const int row = idx >> 3, c16 = idx & 7;
            const uint32_t off = swz(row * 128 + c16 * 16);
            const size_t go = (size_t)(bm + row) * GK + kk + c16 * 8;
            cp16(sAh + off, Ah + go);
            cp16(sAl + off, Al + go);
        }
#pragma unroll
        for (int i = 0; i < 4; i++) {
            const int idx = tid + i * 256;
            const int row = idx >> 3, c16 = idx & 7;
            const uint32_t off = swz(row * 128 + c16 * 16);
            const size_t go = (size_t)(bn + row) * GK + kk + c16 * 8;
            cp16(sBh + off, Bh + go);
            cp16(sBl + off, Bl + go);
        }
        asm volatile("cp.async.commit_group;" ::: "memory");
    };

    prefetch(0, 0);
    prefetch(1, 1);

    for (int c = 0; c < NCH; c++) {
        const int b = c & 1;
        if (c == NCH - 1) asm volatile("cp.async.wait_group 0;" ::: "memory");
        else              asm volatile("cp.async.wait_group 1;" ::: "memory");
        __syncthreads();

        const uint32_t base = smem_base + b * STAGE;
        const uint32_t sAh = base;
        const uint32_t sAl = base + A_BYTES;
        const uint32_t sBh = base + 2 * A_BYTES;
        const uint32_t sBl = sBh + B_BYTES;
#pragma unroll
        for (int ks = 0; ks < 4; ks++) {
            uint32_t Afh[4][4], Bfh[4][4], X[4][4];
            // pass 0: Ah * Bh
#pragma unroll
            for (int mt = 0; mt < 4; mt++)
                ldmx4(Afh[mt], sAh + swz((aRow + mt * 16) * 128 + aCol + ks * 32));
#pragma unroll
            for (int nt2 = 0; nt2 < 4; nt2++)
                ldmx4(Bfh[nt2], sBh + swz((bRow + nt2 * 16) * 128 + bCol + ks * 32));
#pragma unroll
            for (int mt = 0; mt < 4; mt++)
#pragma unroll
                for (int nt = 0; nt < 8; nt++)
                    mma16816(acc[mt][nt], Afh[mt],
                             Bfh[nt >> 1][(nt & 1) * 2],
                             Bfh[nt >> 1][(nt & 1) * 2 + 1]);
            // pass 1: Al * Bh   (X = Afl)
#pragma unroll
            for (int mt = 0; mt < 4; mt++)
                ldmx4(X[mt], sAl + swz((aRow + mt * 16) * 128 + aCol + ks * 32));
#pragma unroll
            for (int mt = 0; mt < 4; mt++)
#pragma unroll
                for (int nt = 0; nt < 8; nt++)
                    mma16816(acc[mt][nt], X[mt],
                             Bfh[nt >> 1][(nt & 1) * 2],
                             Bfh[nt >> 1][(nt & 1) * 2 + 1]);
            // pass 2: Ah * Bl   (X = Bfl, Afl dead)
#pragma unroll
            for (int nt2 = 0; nt2 < 4; nt2++)
                ldmx4(X[nt2], sBl + swz((bRow + nt2 * 16) * 128 + bCol + ks * 32));
#pragma unroll
            for (int mt = 0; mt < 4; mt++)
#pragma unroll
                for (int nt = 0; nt < 8; nt++)
                    mma16816(acc[mt][nt], Afh[mt],
                             X[nt >> 1][(nt & 1) * 2],
                             X[nt >> 1][(nt & 1) * 2 + 1]);
        }
        __syncthreads();
        if (c + 2 < NCH) prefetch(c + 2, b);
    }

    const int erow = (int)(lane >> 2);
    const int ecol = (int)(lane & 3) * 2;
#pragma unroll
    for (int mt = 0; mt < 4; mt++) {
#pragma unroll
        for (int nt = 0; nt < 8; nt++) {
            const int row0 = bm + wm + mt * 16 + erow;
            const int col  = bn + wn + nt * 8 + ecol;
            float2 v0 = make_float2(acc[mt][nt][0], acc[mt][nt][1]);
            float2 v1 = make_float2(acc[mt][nt][2], acc[mt][nt][3]);
            if (doClip) {
                v0.x = fminf(fmaxf(v0.x, -CLIPV), CLIPV);
                v0.y = fminf(fmaxf(v0.y, -CLIPV), CLIPV);
                v1.x = fminf(fmaxf(v1.x, -CLIPV), CLIPV);
                v1.y = fminf(fmaxf(v1.y, -CLIPV), CLIPV);
            }
            *(float2*)(C + (size_t)row0 * ldc + col) = v0;
            *(float2*)(C + (size_t)(row0 + 8) * ldc + col) = v1;
        }
    }
}

// ---------------- LayerNorm -> bf16 hi/lo (for q) ----------------------------
__global__ __launch_bounds__(256) void ln_bf16_kernel(
    const float* __restrict__ src, const float* __restrict__ w,
    const float* __restrict__ b,
    __nv_bfloat16* __restrict__ hi, __nv_bfloat16* __restrict__ lo)
{
    __shared__ float r1[256], r2[256];
    const int row = blockIdx.x;
    const int tid = threadIdx.x;
    const float* x = src + (size_t)row * DQKV;
    float xv[8];
    float s = 0.f, ss = 0.f;
#pragma unroll
    for (int i = 0; i < 8; i++) {
        xv[i] = x[i * 256 + tid];
        s += xv[i];
        ss += xv[i] * xv[i];
    }
    r1[tid] = s; r2[tid] = ss;
    __syncthreads();
    for (int off = 128; off > 0; off >>= 1) {
        if (tid < off) { r1[tid] += r1[tid + off]; r2[tid] += r2[tid + off]; }
        __syncthreads();
    }
    const float mu  = r1[0] * (1.f / DM);
    const float var = r2[0] * (1.f / DM) - mu * mu;
    const float rs  = rsqrtf(var + LNEPS);
#pragma unroll
    for (int i = 0; i < 8; i++) {
        const int d = i * 256 + tid;
        const float y = (xv[i] - mu) * rs * w[d] + b[d];
        __nv_bfloat16 h, l;
        hilo(y, h, l);
        hi[(size_t)row * DM + d] = h;
        lo[(size_t)row * DM + d] = l;
    }
}

// ---------------- Sk mask ------------------------------------------------------
__global__ void mask_zero_kernel() {
    g_insk[blockIdx.x * 256 + threadIdx.x] = 0;
}
__global__ void mask_set_kernel(const int* __restrict__ Sk) {
    g_insk[Sk[blockIdx.x * 256 + threadIdx.x]] = 1;
}

// ---------------- fused LN(k) + gather + blend + bf16 split for K/V ----------
__global__ __launch_bounds__(256) void kv_fuse(
    const float* __restrict__ kc, const float* __restrict__ vc,
    const int* __restrict__ cidx,
    const float* __restrict__ kw, const float* __restrict__ kb)
{
    __shared__ float r1[256], r2[256];
    __shared__ float s_alpha;
    const int t = blockIdx.x;
    const int tid = threadIdx.x;

    // ---- LayerNorm of recomputed k (in registers) ----
    const float* xk = g_qkv + (size_t)t * DQKV + DM;
    float kx[8];
    float s = 0.f, ss = 0.f;
#pragma unroll
    for (int i = 0; i < 8; i++) {
        kx[i] = xk[i * 256 + tid];
        s += kx[i];
        ss += kx[i] * kx[i];
    }
    r1[tid] = s; r2[tid] = ss;
    __syncthreads();
    for (int off = 128; off > 0; off >>= 1) {
        if (tid < off) { r1[tid] += r1[tid + off]; r2[tid] += r2[tid + off]; }
        __syncthreads();
    }
    const float mu  = r1[0] * (1.f / DM);
    const float var = r2[0] * (1.f / DM) - mu * mu;
    const float rs  = rsqrtf(var + LNEPS);
    float krecv[8];
#pragma unroll
    for (int i = 0; i < 8; i++) {
        const int d = i * 256 + tid;
        krecv[i] = (kx[i] - mu) * rs * kw[d] + kb[d];
    }
    __syncthreads();   // r1/r2 reuse below

    const int ci = cidx[t];
    const bool reuse = (ci >= 0);
    const int ci0 = reuse ? ci : 0;
    const bool doBlend = (g_insk[t] != 0);
    const float* vrec = g_qkv + (size_t)t * DQKV + 2 * DM;
    const float* kr   = kc + (size_t)ci0 * DM;
    const float* vr   = vc + (size_t)ci0 * DM;

    float kv[8], vv[8];
    if (doBlend) {
        float krv[8];
        float num = 0.f, den = 0.f;
#pragma unroll
        for (int i = 0; i < 8; i++) {
            const int d = i * 256 + tid;
            krv[i] = kr[d];
            const float df = krecv[i] - krv[i];
            num += df * df;
            den += krv[i] * krv[i];
        }
        r1[tid] = num; r2[tid] = den;
        __syncthreads();
        for (int off = 128; off > 0; off >>= 1) {
            if (tid < off) { r1[tid] += r1[tid + off]; r2[tid] += r2[tid + off]; }
            __syncthreads();
        }
        if (tid == 0) {
            float a = r1[0] / fmaxf(r2[0], WCAEPS);
            s_alpha = fminf(fmaxf(a, 0.f), 1.f);
        }
        __syncthreads();
        const float alpha = s_alpha;
#pragma unroll
        for (int i = 0; i < 8; i++) {
            const int d = i * 256 + tid;
            kv[i] = alpha * krecv[i] + (1.f - alpha) * krv[i];
            vv[i] = alpha * vrec[d]  + (1.f - alpha) * vr[d];
        }
    } else if (reuse) {
#pragma unroll
        for (int i = 0; i < 8; i++) {
            const int d = i * 256 + tid;
            kv[i] = kr[d]; vv[i] = vr[d];
        }
    } else {
#pragma unroll
        for (int i = 0; i < 8; i++) {
            const int d = i * 256 + tid;
            kv[i] = krecv[i]; vv[i] = vrec[d];
        }
    }
#pragma unroll
    for (int i = 0; i < 8; i++) {
        const size_t d = (size_t)t * DM + i * 256 + tid;
        __nv_bfloat16 h, l;
        hilo(kv[i], h, l);
        g_kh[d] = h; g_kl[d] = l;
        hilo(vv[i], h, l);
        g_vh[d] = h; g_vl[d] = l;
    }
}

// ---------------- FlashAttention-2 on mma.sync, split-bf16 -------------------
#define STR 272
#define QSM (2 * 128 * STR)
#define KVSM (4 * 64 * STR)
#define ATT_SMEM (QSM + 2 * KVSM)

__global__ __launch_bounds__(256, 1) void attn_mma()
{
    extern __shared__ __align__(1024) char asmem[];
    const uint32_t sb = smem_u32(asmem);
    const int tid = threadIdx.x;
    const int wid = tid >> 5, ln = tid & 31;
    const int h = blockIdx.y;
    const int qt = (int)(gridDim.x - 1 - blockIdx.x);
    const int t0 = qt * 128;
    const int m0 = wid * 16;
    const int g = ln >> 2, qd = ln & 3;
    const int lq = ln >> 3, lr = ln & 7;
    const float slope = exp2f(-0.5f * (float)(h + 1));
    const float scl = 0.08838834764831845f;
    const int lastj = 2 * qt + 1;

    const uint32_t sQh = sb, sQl = sb + 128 * STR;

    {
        const __nv_bfloat16* S0 = g_qh + (size_t)t0 * DM + h * HD;
        const __nv_bfloat16* S1 = g_ql + (size_t)t0 * DM + h * HD;
#pragma unroll
        for (int i = 0; i < 8; i++) {
            const int idx = tid + i * 256;
            const int row = idx >> 4, c = idx & 15;
            cp16(sQh + row * STR + c * 16, S0 + (size_t)row * DM + c * 8);
            cp16(sQl + row * STR + c * 16, S1 + (size_t)row * DM + c * 8);
        }
        asm volatile("cp.async.commit_group;" ::: "memory");
    }

    auto loadKV = [&](int jt, int s) {
        const int j0 = jt * 64;
        const uint32_t base = sb + QSM + s * KVSM;
        const size_t goff = (size_t)j0 * DM + h * HD;
        const __nv_bfloat16* P0 = g_kh + goff;
        const __nv_bfloat16* P1 = g_kl + goff;
        const __nv_bfloat16* P2 = g_vh + goff;
        const __nv_bfloat16* P3 = g_vl + goff;
#pragma unroll
        for (int i = 0; i < 4; i++) {
            const int idx = tid + i * 256;
            const int row = idx >> 4, c = idx & 15;
            const uint32_t d = base + row * STR + c * 16;
            const size_t o = (size_t)row * DM + c * 8;
            cp16(d,             P0 + o);
            cp16(d + 64 * STR,  P1 + o);
            cp16(d + 128 * STR, P2 + o);
            cp16(d + 192 * STR, P3 + o);
        }
        asm volatile("cp.async.commit_group;" ::: "memory");
    };
    loadKV(0, 0);
    loadKV(1, 1);

    const uint32_t aAB = (uint32_t)((m0 + (lq & 1) * 8 + lr) * STR + (lq >> 1) * 16);
    const uint32_t bAB = (uint32_t)(((lq >> 1) * 8 + lr) * STR + (lq & 1) * 16);
    const uint32_t vAB = (uint32_t)(((lq & 1) * 8 + lr) * STR + (lq >> 1) * 16);

    float accO[16][4];
#pragma unroll
    for (int i = 0; i < 16; i++)
#pragma unroll
        for (int j = 0; j < 4; j++) accO[i][j] = 0.f;
    float mS0 = -1e30f, mS1 = -1e30f, lS0 = 0.f, lS1 = 0.f;

    for (int jt = 0; jt <= lastj; jt++) {
        const int s = jt & 1;
        if (jt == lastj) asm volatile("cp.async.wait_group 0;" ::: "memory");
        else             asm volatile("cp.async.wait_group 1;" ::: "memory");
        __syncthreads();
        const uint32_t kh = sb + QSM + s * KVSM;
        const uint32_t kl = kh + 64 * STR;
        const uint32_t vh = kh + 128 * STR;
        const uint32_t vl = kh + 192 * STR;

        float accS[8][4];
#pragma unroll
        for (int i = 0; i < 8; i++)
#pragma unroll
            for (int j = 0; j < 4; j++) accS[i][j] = 0.f;
#pragma unroll
        for (int kc = 0; kc < 8; kc++) {
            uint32_t aQh[4], aQl[4];
            ldmx4(aQh, sQh + aAB + kc * 32);
            ldmx4(aQl, sQl + aAB + kc * 32);
#pragma unroll
            for (int ntp = 0; ntp < 4; ntp++) {
                uint32_t bKh[4], bKl[4];
                ldmx4(bKh, kh + bAB + ntp * (16 * STR) + kc * 32);
                ldmx4(bKl, kl + bAB + ntp * (16 * STR) + kc * 32);
                mma16816(accS[2 * ntp],     aQh, bKh[0], bKh[1]);
                mma16816(accS[2 * ntp + 1], aQh, bKh[2], bKh[3]);
                mma16816(accS[2 * ntp],     aQl, bKh[0], bKh[1]);
                mma16816(accS[2 * ntp + 1], aQl, bKh[2], bKh[3]);
                mma16816(accS[2 * ntp],     aQh, bKl[0], bKl[1]);
                mma16816(accS[2 * ntp + 1], aQh, bKl[2], bKl[3]);
            }
        }

        const int j0 = jt * 64;
        const int qi0 = t0 + m0 + g;
        const int qi1 = qi0 + 8;
        float mx0 = -1e30f, mx1 = -1e30f;
#pragma unroll
        for (int nt = 0; nt < 8; nt++) {
            const int kj = j0 + nt * 8 + qd * 2;
            float s0 = accS[nt][0] * scl + slope * (float)(kj - qi0);
            float s1 = accS[nt][1] * scl + slope * (float)(kj + 1 - qi0);
            float s2 = accS[nt][2] * scl + slope * (float)(kj - qi1);
            float s3 = accS[nt][3] * scl + slope * (float)(kj + 1 - qi1);
            if (kj > qi0)     s0 = -1e30f;
            if (kj + 1 > qi0) s1 = -1e30f;
            if (kj > qi1)     s2 = -1e30f;
            if (kj + 1 > qi1) s3 = -1e30f;
            accS[nt][0] = s0; accS[nt][1] = s1; accS[nt][2] = s2; accS[nt][3] = s3;
            mx0 = fmaxf(mx0, fmaxf(s0, s1));
            mx1 = fmaxf(mx1, fmaxf(s2, s3));
        }
        mx0 = fmaxf(mx0, __shfl_xor_sync(0xffffffffu, mx0, 1));
        mx0 = fmaxf(mx0, __shfl_xor_sync(0xffffffffu, mx0, 2));
        mx1 = fmaxf(mx1, __shfl_xor_sync(0xffffffffu, mx1, 1));
        mx1 = fmaxf(mx1, __shfl_xor_sync(0xffffffffu, mx1, 2));
        const float mN0 = fmaxf(mS0, mx0), mN1 = fmaxf(mS1, mx1);
        const float sc0 = __expf(mS0 - mN0), sc1 = __expf(mS1 - mN1);
        float sum0 = 0.f, sum1 = 0.f;
#pragma unroll
        for (int nt = 0; nt < 8; nt++) {
            accS[nt][0] = __expf(accS[nt][0] - mN0);
            accS[nt][1] = __expf(accS[nt][1] - mN0);
            accS[nt][2] = __expf(accS[nt][2] - mN1);
            accS[nt][3] = __expf(accS[nt][3] - mN1);
            sum0 += accS[nt][0] + accS[nt][1];
            sum1 += accS[nt][2] + accS[nt][3];
        }
        sum0 += __shfl_xor_sync(0xffffffffu, sum0, 1);
        sum0 += __shfl_xor_sync(0xffffffffu, sum0, 2);
        sum1 += __shfl_xor_sync(0xffffffffu, sum1, 1);
        sum1 += __shfl_xor_sync(0xffffffffu, sum1, 2);
        lS0 = lS0 * sc0 + sum0;
        lS1 = lS1 * sc1 + sum1;
        mS0 = mN0; mS1 = mN1;
#pragma unroll
        for (int nt = 0; nt < 16; nt++) {
            accO[nt][0] *= sc0; accO[nt][1] *= sc0;
            accO[nt][2] *= sc1; accO[nt][3] *= sc1;
        }

        uint32_t aPh[4][4], aPl[4][4];
#pragma unroll
        for (int kc = 0; kc < 4; kc++) {
#pragma unroll
            for (int e = 0; e < 4; e++) {
                const int nt = 2 * kc + (e >> 1);
                const int b0 = (e & 1) * 2;
                const float p0 = accS[nt][b0], p1 = accS[nt][b0 + 1];
                const __nv_bfloat16 h0 = __float2bfloat16_rn(p0);
                const __nv_bfloat16 h1 = __float2bfloat16_rn(p1);
                __nv_bfloat162 hh = __halves2bfloat162(h0, h1);
                memcpy(&aPh[kc][e], &hh, 4);
                aPl[kc][e] = pk_bf2(p0 - __bfloat162float(h0),
                                    p1 - __bfloat162float(h1));
            }
        }

#pragma unroll
        for (int ntp = 0; ntp < 8; ntp++) {
#pragma unroll
            for (int kc = 0; kc < 4; kc++) {
                uint32_t bVh[4], bVl[4];
                ldmx4t(bVh, vh + vAB + kc * (16 * STR) + ntp * 32);
                ldmx4t(bVl, vl + vAB + kc * (16 * STR) + ntp * 32);
                mma16816(accO[2 * ntp],     aPh[kc], bVh[0], bVh[1]);
                mma16816(accO[2 * ntp + 1], aPh[kc], bVh[2], bVh[3]);
                mma16816(accO[2 * ntp],     aPl[kc], bVh[0], bVh[1]);
                mma16816(accO[2 * ntp + 1], aPl[kc], bVh[2], bVh[3]);
                mma16816(accO[2 * ntp],     aPh[kc], bVl[0], bVl[1]);
                mma16816(accO[2 * ntp + 1], aPh[kc], bVl[2], bVl[3]);
            }
        }
        __syncthreads();
        if (jt + 2 <= lastj) loadKV(jt + 2, s);
    }

    // ---- epilogue: write bf16 hi/lo directly (feeds gemm2) ----
    const float i0 = 1.f / lS0, i1 = 1.f / lS1;
    const size_t base0 = (size_t)(t0 + m0 + g) * DM + h * HD + qd * 2;
    const size_t base1 = base0 + (size_t)8 * DM;
#pragma unroll
    for (int nt = 0; nt < 16; nt++) {
        float a0 = accO[nt][0] * i0, a1 = accO[nt][1] * i0;
        float a2 = accO[nt][2] * i1, a3 = accO[nt][3] * i1;
        __nv_bfloat16 h0, h1, h2, h3, l0, l1, l2, l3;
        hilo(a0, h0, l0); hilo(a1, h1, l1);
        hilo(a2, h2, l2); hilo(a3, h3, l3);
        *(__nv_bfloat162*)(g_at_h + base0 + nt * 8) = __halves2bfloat162(h0, h1);
        *(__nv_bfloat162*)(g_at_l + base0 + nt * 8) = __halves2bfloat162(l0, l1);
        *(__nv_bfloat162*)(g_at_h + base1 + nt * 8) = __halves2bfloat162(h2, h3);
        *(__nv_bfloat162*)(g_at_l + base1 + nt * 8) = __halves2bfloat162(l2, l3);
    }
}

// ---------------- launch ------------------------------------------------------
extern "C" void kernel_launch(void* const* d_in, const int* in_sizes, int n_in,
                              void* d_out, int out_size)
{
    const float* hs   = (const float*)d_in[0];
    const float* Wqkv = (const float*)d_in[1];
    const float* qw   = (const float*)d_in[2];
    const float* qb   = (const float*)d_in[3];
    const float* kw   = (const float*)d_in[4];
    const float* kb   = (const float*)d_in[5];
    const float* outw = (const float*)d_in[6];
    const float* kc   = (const float*)d_in[7];
    const float* vc   = (const float*)d_in[8];
    const int*   cidx = (const int*)d_in[9];
    const int*   Sk   = (const int*)d_in[10];
    float* out = (float*)d_out;

    float *p_qkv;
    cudaGetSymbolAddress((void**)&p_qkv,  g_qkv);
    __nv_bfloat16 *hs_h, *hs_l, *w1_h, *w1_l, *ow_h, *ow_l, *at_h, *at_l, *qh_, *ql_;
    cudaGetSymbolAddress((void**)&hs_h, g_hs_h);
    cudaGetSymbolAddress((void**)&hs_l, g_hs_l);
    cudaGetSymbolAddress((void**)&w1_h, g_w1_h);
    cudaGetSymbolAddress((void**)&w1_l, g_w1_l);
    cudaGetSymbolAddress((void**)&ow_h, g_ow_h);
    cudaGetSymbolAddress((void**)&ow_l, g_ow_l);
    cudaGetSymbolAddress((void**)&at_h, g_at_h);
    cudaGetSymbolAddress((void**)&at_l, g_at_l);
    cudaGetSymbolAddress((void**)&qh_, g_qh);
    cudaGetSymbolAddress((void**)&ql_, g_ql);

    cudaFuncSetAttribute(gemm_mma, cudaFuncAttributeMaxDynamicSharedMemorySize,
                         GSM_BYTES);
    cudaFuncSetAttribute(attn_mma, cudaFuncAttributeMaxDynamicSharedMemorySize,
                         ATT_SMEM);

    // 0. bf16 hi/lo splits of GEMM operands (fused, 1 launch)
    const int n_hs = (TT * DM) / 4096;                 // 1024
    const int n_w1 = (int)(((size_t)DQKV * DM) / 4096); // 3072
    const int n_ow = (DM * DM) / 4096;                 // 1024
    split3_kernel<<<n_hs + n_w1 + n_ow, 256>>>(
        hs, hs_h, hs_l, Wqkv, w1_h, w1_l, outw, ow_h, ow_l, n_hs, n_w1);
    // 1. QKV projection + clip
    gemm_mma<<<dim3(DQKV / 128, TT / 256), 256, GSM_BYTES>>>(
        hs_h, hs_l, w1_h, w1_l, p_qkv, DQKV, 1);
    // 2. LayerNorm q -> bf16 hi/lo
    ln_bf16_kernel<<<TT, 256>>>(p_qkv + 0, qw, qb, qh_, ql_);
    // 3. Sk mask
    mask_zero_kernel<<<TT / 256, 256>>>();
    mask_set_kernel<<<KSK / 256, 256>>>(Sk);
    // 4. fused LN(k) + gather + blend + split -> kh/kl/vh/vl
    kv_fuse<<<TT, 256>>>(kc, vc, cidx, kw, kb);
    // 5. attention (writes at_h/at_l bf16 hi/lo)
    attn_mma<<<dim3(TT / 128, NH), 256, ATT_SMEM>>>();
    // 6. output projection
    gemm_mma<<<dim3(DM / 128, TT / 256), 256, GSM_BYTES>>>(
        at_h, at_l, ow_h, ow_l, out, DM, 0);
}

// round 17
// speedup vs baseline: 1.0263x; 1.0105x over previous
#include <cuda_runtime.h>
#include <cuda_bf16.h>
#include <math.h>
#include <stdint.h>
#include <string.h>

#define TT 2048
#define DM 2048
#define NH 16
#define HD 128
#define DQKV 6144
#define KSK 512
#define CLIPV 8.0f
#define LNEPS 1e-5f
#define WCAEPS 1e-6f

// ---------------- scratch (device globals; no allocation allowed) ----------
__device__ __align__(128) float g_qkv[(size_t)TT * DQKV];
// bf16 hi/lo operand copies (GEMMs)
__device__ __align__(128) __nv_bfloat16 g_hs_h[(size_t)TT * DM];
__device__ __align__(128) __nv_bfloat16 g_hs_l[(size_t)TT * DM];
__device__ __align__(128) __nv_bfloat16 g_w1_h[(size_t)DQKV * DM];
__device__ __align__(128) __nv_bfloat16 g_w1_l[(size_t)DQKV * DM];
__device__ __align__(128) __nv_bfloat16 g_ow_h[(size_t)DM * DM];
__device__ __align__(128) __nv_bfloat16 g_ow_l[(size_t)DM * DM];
__device__ __align__(128) __nv_bfloat16 g_at_h[(size_t)TT * DM];
__device__ __align__(128) __nv_bfloat16 g_at_l[(size_t)TT * DM];
// bf16 hi/lo attention operands
__device__ __align__(128) __nv_bfloat16 g_qh[(size_t)TT * DM];
__device__ __align__(128) __nv_bfloat16 g_ql[(size_t)TT * DM];
__device__ __align__(128) __nv_bfloat16 g_kh[(size_t)TT * DM];
__device__ __align__(128) __nv_bfloat16 g_kl[(size_t)TT * DM];
__device__ __align__(128) __nv_bfloat16 g_vh[(size_t)TT * DM];
__device__ __align__(128) __nv_bfloat16 g_vl[(size_t)TT * DM];

// ---------------- helpers ----------------------------------------------------
__device__ __forceinline__ uint32_t smem_u32(const void* p) {
    uint32_t a;
    asm("{ .reg .u64 t; cvta.to.shared.u64 t, %1; cvt.u32.u64 %0, t; }"
        : "=r"(a) : "l"(p));
    return a;
}
__device__ __forceinline__ uint32_t swz(uint32_t off) {
    return off ^ ((off >> 3) & 0x70);
}
__device__ __forceinline__ void cp16(uint32_t saddr, const void* gaddr) {
    asm volatile("cp.async.cg.shared.global [%0], [%1], 16;"
                 :: "r"(saddr), "l"(gaddr) : "memory");
}
__device__ __forceinline__ void ldmx4(uint32_t* d, uint32_t addr) {
    asm volatile("ldmatrix.sync.aligned.m8n8.x4.shared.b16 {%0,%1,%2,%3}, [%4];"
                 : "=r"(d[0]), "=r"(d[1]), "=r"(d[2]), "=r"(d[3]) : "r"(addr));
}
__device__ __forceinline__ void ldmx4t(uint32_t* d, uint32_t addr) {
    asm volatile("ldmatrix.sync.aligned.m8n8.x4.trans.shared.b16 {%0,%1,%2,%3}, [%4];"
                 : "=r"(d[0]), "=r"(d[1]), "=r"(d[2]), "=r"(d[3]) : "r"(addr));
}
__device__ __forceinline__ void mma16816(float* c, const uint32_t* a,
                                         uint32_t b0, uint32_t b1) {
    asm volatile("mma.sync.aligned.m16n8k16.row.col.f32.bf16.bf16.f32 "
                 "{%0,%1,%2,%3}, {%4,%5,%6,%7}, {%8,%9}, {%0,%1,%2,%3};"
                 : "+f"(c[0]), "+f"(c[1]), "+f"(c[2]), "+f"(c[3])
                 : "r"(a[0]), "r"(a[1]), "r"(a[2]), "r"(a[3]),
                   "r"(b0), "r"(b1));
}
__device__ __forceinline__ uint32_t pk_bf2(float a, float b) {
    __nv_bfloat162 v = __floats2bfloat162_rn(a, b);
    uint32_t r; memcpy(&r, &v, 4);
    return r;
}
__device__ __forceinline__ void hilo(float x, __nv_bfloat16& h, __nv_bfloat16& l) {
    h = __float2bfloat16_rn(x);
    l = __float2bfloat16_rn(x - __bfloat162float(h));
}

// ---------------- fused fp32 -> bf16 hi/lo split (3 tensors, 1 launch) -------
__global__ __launch_bounds__(256) void split3_kernel(
    const float* __restrict__ s0, __nv_bfloat16* __restrict__ h0p,
    __nv_bfloat16* __restrict__ l0p,
    const float* __restrict__ s1, __nv_bfloat16* __restrict__ h1p,
    __nv_bfloat16* __restrict__ l1p,
    const float* __restrict__ s2, __nv_bfloat16* __restrict__ h2p,
    __nv_bfloat16* __restrict__ l2p,
    int n0, int n1)
{
    int b = blockIdx.x;
    const float* src;
    __nv_bfloat16 *hi, *lo;
    if (b < n0)           { src = s0; hi = h0p; lo = l0p; }
    else if (b < n0 + n1) { src = s1; hi = h1p; lo = l1p; b -= n0; }
    else                  { src = s2; hi = h2p; lo = l2p; b -= n0 + n1; }
    const size_t i = ((size_t)b * 256 + threadIdx.x) * 16;
    float4 f0 = *(const float4*)(src + i);
    float4 f1 = *(const float4*)(src + i + 4);
    float4 f2 = *(const float4*)(src + i + 8);
    float4 f3 = *(const float4*)(src + i + 12);
    float fv[16] = {f0.x, f0.y, f0.z, f0.w, f1.x, f1.y, f1.z, f1.w,
                    f2.x, f2.y, f2.z, f2.w, f3.x, f3.y, f3.z, f3.w};
    uint32_t hv[8], lv[8];
#pragma unroll
    for (int j = 0; j < 8; j++) {
        __nv_bfloat16 h0, h1, l0, l1;
        hilo(fv[2 * j], h0, l0);
        hilo(fv[2 * j + 1], h1, l1);
        __nv_bfloat162 hh = __halves2bfloat162(h0, h1);
        __nv_bfloat162 ll = __halves2bfloat162(l0, l1);
        memcpy(&hv[j], &hh, 4);
        memcpy(&lv[j], &ll, 4);
    }
    *(uint4*)(hi + i)     = make_uint4(hv[0], hv[1], hv[2], hv[3]);
    *(uint4*)(hi + i + 8) = make_uint4(hv[4], hv[5], hv[6], hv[7]);
    *(uint4*)(lo + i)     = make_uint4(lv[0], lv[1], lv[2], lv[3]);
    *(uint4*)(lo + i + 8) = make_uint4(lv[4], lv[5], lv[6], lv[7]);
}

// ================= HMMA split-bf16 GEMM, shared-operand, PERSISTENT ==========
// 256 threads (8 warps, 4x2), tile 256x128, warp tile 64x64, BK=64,
// 2-stage 96KB pipeline. Persistent CTAs: grid=148 (gemm1) loops flat tile
// index with stride gridDim.x -> kills the 2.59-wave quantization tail.
#define GK 2048
#define GBK 64
#define NCH 32
#define A_BYTES  32768
#define B_BYTES  16384
#define STAGE (2 * A_BYTES + 2 * B_BYTES)   // 98304
#define GSM_BYTES (2 * STAGE)               // 196608

__global__ __launch_bounds__(256, 1) void gemm_mma(
    const __nv_bfloat16* __restrict__ Ah, const __nv_bfloat16* __restrict__ Al,
    const __nv_bfloat16* __restrict__ Bh, const __nv_bfloat16* __restrict__ Bl,
    float* __restrict__ C, int ldc, int doClip, int ntiles, int nx)
{
    extern __shared__ __align__(1024) char smem[];
    const uint32_t smem_base = smem_u32(smem);
    const int tid = threadIdx.x;
    const int wid = tid >> 5;
    const int lane = tid & 31;
    const int wm = (wid >> 1) * 64;
    const int wn = (wid & 1) * 64;
    const uint32_t lq = lane >> 3, lr = lane & 7;
    const int aRowB = wm + (lq & 1) * 8 + lr;
    const int aCol  = (lq >> 1) * 16;
    const int bRowB = wn + (lq >> 1) * 8 + lr;
    const int bCol  = (lq & 1) * 16;

    for (int t = blockIdx.x; t < ntiles; t += gridDim.x) {
        const int bm = (t / nx) * 256;
        const int bn = (t % nx) * 128;

        float acc[4][8][4];
#pragma unroll
        for (int i = 0; i < 4; i++)
#pragma unroll
            for (int j = 0; j < 8; j++)
#pragma unroll
                for (int k = 0; k < 4; k++) acc[i][j][k] = 0.f;

        auto prefetch = [&](int c, int b) {
            const int kk = c * GBK;
            const uint32_t base = smem_base + b * STAGE;
            const uint32_t sAh = base;
            const uint32_t sAl = base + A_BYTES;
            const uint32_t sBh = base + 2 * A_BYTES;
            const uint32_t sBl = sBh + B_BYTES;
#pragma unroll
            for (int i = 0; i < 8; i++) {
                const int idx = tid + i * 256;
                const int row = idx >> 3, c16 = idx & 7;
                const uint32_t off = swz(row * 128 + c16 * 16);
                const size_t go = (size_t)(bm + row) * GK + kk + c16 * 8;
                cp16(sAh + off, Ah + go);
                cp16(sAl + off, Al + go);
            }
#pragma unroll
            for (int i = 0; i < 4; i++) {
                const int idx = tid + i * 256;
                const int row = idx >> 3, c16 = idx & 7;
                const uint32_t off = swz(row * 128 + c16 * 16);
                const size_t go = (size_t)(bn + row) * GK + kk + c16 * 8;
                cp16(sBh + off, Bh + go);
                cp16(sBl + off, Bl + go);
            }
            asm volatile("cp.async.commit_group;" ::: "memory");
        };

        prefetch(0, 0);
        prefetch(1, 1);

        for (int c = 0; c < NCH; c++) {
            const int b = c & 1;
            if (c == NCH - 1) asm volatile("cp.async.wait_group 0;" ::: "memory");
            else              asm volatile("cp.async.wait_group 1;" ::: "memory");
            __syncthreads();

            const uint32_t base = smem_base + b * STAGE;
            const uint32_t sAh = base;
            const uint32_t sAl = base + A_BYTES;
            const uint32_t sBh = base + 2 * A_BYTES;
            const uint32_t sBl = sBh + B_BYTES;
#pragma unroll
            for (int ks = 0; ks < 4; ks++) {
                uint32_t Afh[4][4], Bfh[4][4], X[4][4];
#pragma unroll
                for (int mt = 0; mt < 4; mt++)
                    ldmx4(Afh[mt], sAh + swz((aRowB + mt * 16) * 128 + aCol + ks * 32));
#pragma unroll
                for (int nt2 = 0; nt2 < 4; nt2++)
                    ldmx4(Bfh[nt2], sBh + swz((bRowB + nt2 * 16) * 128 + bCol + ks * 32));
#pragma unroll
                for (int mt = 0; mt < 4; mt++)
#pragma unroll
                    for (int nt = 0; nt < 8; nt++)
                        mma16816(acc[mt][nt], Afh[mt],
                                 Bfh[nt >> 1][(nt & 1) * 2],
                                 Bfh[nt >> 1][(nt & 1) * 2 + 1]);
#pragma unroll
                for (int mt = 0; mt < 4; mt++)
                    ldmx4(X[mt], sAl + swz((aRowB + mt * 16) * 128 + aCol + ks * 32));
#pragma unroll
                for (int mt = 0; mt < 4; mt++)
#pragma unroll
                    for (int nt = 0; nt < 8; nt++)
                        mma16816(acc[mt][nt], X[mt],
                                 Bfh[nt >> 1][(nt & 1) * 2],
                                 Bfh[nt >> 1][(nt & 1) * 2 + 1]);
#pragma unroll
                for (int nt2 = 0; nt2 < 4; nt2++)
                    ldmx4(X[nt2], sBl + swz((bRowB + nt2 * 16) * 128 + bCol + ks * 32));
#pragma unroll
                for (int mt = 0; mt < 4; mt++)
#pragma unroll
                    for (int nt = 0; nt < 8; nt++)
                        mma16816(acc[mt][nt], Afh[mt],
                                 X[nt >> 1][(nt & 1) * 2],
                                 X[nt >> 1][(nt & 1) * 2 + 1]);
            }
            __syncthreads();
            if (c + 2 < NCH) prefetch(c + 2, b);
        }

        const int erow = (int)(lane >> 2);
        const int ecol = (int)(lane & 3) * 2;
#pragma unroll
        for (int mt = 0; mt < 4; mt++) {
#pragma unroll
            for (int nt = 0; nt < 8; nt++) {
                const int row0 = bm + wm + mt * 16 + erow;
                const int col  = bn + wn + nt * 8 + ecol;
                float2 v0 = make_float2(acc[mt][nt][0], acc[mt][nt][1]);
                float2 v1 = make_float2(acc[mt][nt][2], acc[mt][nt][3]);
                if (doClip) {
                    v0.x = fminf(fmaxf(v0.x, -CLIPV), CLIPV);
                    v0.y = fminf(fmaxf(v0.y, -CLIPV), CLIPV);
                    v1.x = fminf(fmaxf(v1.x, -CLIPV), CLIPV);
                    v1.y = fminf(fmaxf(v1.y, -CLIPV), CLIPV);
                }
                *(float2*)(C + (size_t)row0 * ldc + col) = v0;
                *(float2*)(C + (size_t)(row0 + 8) * ldc + col) = v1;
            }
        }
        // no extra sync needed: next tile's prefetch targets smem not read by
        // the epilogue, and the top-of-chunk sync orders it vs old math.
    }
}

// ---------------- fused qkv post-processing (per token) ----------------------
// LN(q) -> qh/ql ; LN(k) -> blend(gather, Sk alpha) -> kh/kl ; v -> vh/vl.
__global__ __launch_bounds__(256) void qkv_post(
    const float* __restrict__ kc, const float* __restrict__ vc,
    const int* __restrict__ cidx, const int* __restrict__ Sk,
    const float* __restrict__ qw, const float* __restrict__ qb,
    const float* __restrict__ kw, const float* __restrict__ kb)
{
    __shared__ float4 red[256];
    __shared__ float r1[256], r2[256];
    __shared__ float s_alpha;
    __shared__ int s_flag;
    const int t = blockIdx.x;
    const int tid = threadIdx.x;

    // Sk membership (512 entries, 2 per thread)
    if (tid == 0) s_flag = 0;
    __syncthreads();
    if (Sk[tid] == t || Sk[tid + 256] == t) s_flag = 1;

    // dual LN reduction for q and k
    const float* xq = g_qkv + (size_t)t * DQKV;
    const float* xk = xq + DM;
    float qx[8], kx[8];
    float sq = 0.f, ssq = 0.f, sk = 0.f, ssk = 0.f;
#pragma unroll
    for (int i = 0; i < 8; i++) {
        qx[i] = xq[i * 256 + tid];
        kx[i] = xk[i * 256 + tid];
        sq += qx[i]; ssq += qx[i] * qx[i];
        sk += kx[i]; ssk += kx[i] * kx[i];
    }
    red[tid] = make_float4(sq, ssq, sk, ssk);
    __syncthreads();
    for (int off = 128; off > 0; off >>= 1) {
        if (tid < off) {
            float4 a = red[tid], b = red[tid + off];
            red[tid] = make_float4(a.x + b.x, a.y + b.y, a.z + b.z, a.w + b.w);
        }
        __syncthreads();
    }
    const float4 tot = red[0];
    const float muq = tot.x * (1.f / DM);
    const float rsq = rsqrtf(tot.y * (1.f / DM) - muq * muq + LNEPS);
    const float muk = tot.z * (1.f / DM);
    const float rsk = rsqrtf(tot.w * (1.f / DM) - muk * muk + LNEPS);

    float krecv[8];
#pragma unroll
    for (int i = 0; i < 8; i++) {
        const int d = i * 256 + tid;
        const float yq = (qx[i] - muq) * rsq * qw[d] + qb[d];
        __nv_bfloat16 h, l;
        hilo(yq, h, l);
        g_qh[(size_t)t * DM + d] = h;
        g_ql[(size_t)t * DM + d] = l;
        krecv[i] = (kx[i] - muk) * rsk * kw[d] + kb[d];
    }

    const int ci = cidx[t];
    const bool reuse = (ci >= 0);
    const int ci0 = reuse ? ci : 0;
    const bool doBlend = (s_flag != 0);
    const float* vrec = g_qkv + (size_t)t * DQKV + 2 * DM;
    const float* kr   = kc + (size_t)ci0 * DM;
    const float* vr   = vc + (size_t)ci0 * DM;

    float kv[8], vv[8];
    if (doBlend) {
        float krv[8];
        float num = 0.f, den = 0.f;
#pragma unroll
        for (int i = 0; i < 8; i++) {
            const int d = i * 256 + tid;
            krv[i] = kr[d];
            const float df = krecv[i] - krv[i];
            num += df * df;
            den += krv[i] * krv[i];
        }
        r1[tid] = num; r2[tid] = den;
        __syncthreads();
        for (int off = 128; off > 0; off >>= 1) {
            if (tid < off) { r1[tid] += r1[tid + off]; r2[tid] += r2[tid + off]; }
            __syncthreads();
        }
        if (tid == 0) {
            float a = r1[0] / fmaxf(r2[0], WCAEPS);
            s_alpha = fminf(fmaxf(a, 0.f), 1.f);
        }
        __syncthreads();
        const float alpha = s_alpha;
#pragma unroll
        for (int i = 0; i < 8; i++) {
            const int d = i * 256 + tid;
            kv[i] = alpha * krecv[i] + (1.f - alpha) * krv[i];
            vv[i] = alpha * vrec[d]  + (1.f - alpha) * vr[d];
        }
    } else if (reuse) {
#pragma unroll
        for (int i = 0; i < 8; i++) {
            const int d = i * 256 + tid;
            kv[i] = kr[d]; vv[i] = vr[d];
        }
    } else {
#pragma unroll
        for (int i = 0; i < 8; i++) {
            const int d = i * 256 + tid;
            kv[i] = krecv[i]; vv[i] = vrec[d];
        }
    }
#pragma unroll
    for (int i = 0; i < 8; i++) {
        const size_t d = (size_t)t * DM + i * 256 + tid;
        __nv_bfloat16 h, l;
        hilo(kv[i], h, l);
        g_kh[d] = h; g_kl[d] = l;
        hilo(vv[i], h, l);
        g_vh[d] = h; g_vl[d] = l;
    }
}

// ---------------- FlashAttention-2 on mma.sync, split-bf16 -------------------
#define STR 272
#define QSM (2 * 128 * STR)
#define KVSM (4 * 64 * STR)
#define ATT_SMEM (QSM + 2 * KVSM)

__global__ __launch_bounds__(256, 1) void attn_mma()
{
    extern __shared__ __align__(1024) char asmem[];
    const uint32_t sb = smem_u32(asmem);
    const int tid = threadIdx.x;
    const int wid = tid >> 5, ln = tid & 31;
    const int h = blockIdx.y;
    const int qt = (int)(gridDim.x - 1 - blockIdx.x);
    const int t0 = qt * 128;
    const int m0 = wid * 16;
    const int g = ln >> 2, qd = ln & 3;
    const int lq = ln >> 3, lr = ln & 7;
    const float slope = exp2f(-0.5f * (float)(h + 1));
    const float scl = 0.08838834764831845f;
    const int lastj = 2 * qt + 1;

    const uint32_t sQh = sb, sQl = sb + 128 * STR;

    {
        const __nv_bfloat16* S0 = g_qh + (size_t)t0 * DM + h * HD;
        const __nv_bfloat16* S1 = g_ql + (size_t)t0 * DM + h * HD;
#pragma unroll
        for (int i = 0; i < 8; i++) {
            const int idx = tid + i * 256;
            const int row = idx >> 4, c = idx & 15;
            cp16(sQh + row * STR + c * 16, S0 + (size_t)row * DM + c * 8);
            cp16(sQl + row * STR + c * 16, S1 + (size_t)row * DM + c * 8);
        }
        asm volatile("cp.async.commit_group;" ::: "memory");
    }

    auto loadKV = [&](int jt, int s) {
        const int j0 = jt * 64;
        const uint32_t base = sb + QSM + s * KVSM;
        const size_t goff = (size_t)j0 * DM + h * HD;
        const __nv_bfloat16* P0 = g_kh + goff;
        const __nv_bfloat16* P1 = g_kl + goff;
        const __nv_bfloat16* P2 = g_vh + goff;
        const __nv_bfloat16* P3 = g_vl + goff;
#pragma unroll
        for (int i = 0; i < 4; i++) {
            const int idx = tid + i * 256;
            const int row = idx >> 4, c = idx & 15;
            const uint32_t d = base + row * STR + c * 16;
            const size_t o = (size_t)row * DM + c * 8;
            cp16(d,             P0 + o);
            cp16(d + 64 * STR,  P1 + o);
            cp16(d + 128 * STR, P2 + o);
            cp16(d + 192 * STR, P3 + o);
        }
        asm volatile("cp.async.commit_group;" ::: "memory");
    };
    loadKV(0, 0);
    loadKV(1, 1);

    const uint32_t aAB = (uint32_t)((m0 + (lq & 1) * 8 + lr) * STR + (lq >> 1) * 16);
    const uint32_t bAB = (uint32_t)(((lq >> 1) * 8 + lr) * STR + (lq & 1) * 16);
    const uint32_t vAB = (uint32_t)(((lq & 1) * 8 + lr) * STR + (lq >> 1) * 16);

    float accO[16][4];
#pragma unroll
    for (int i = 0; i < 16; i++)
#pragma unroll
        for (int j = 0; j < 4; j++) accO[i][j] = 0.f;
    float mS0 = -1e30f, mS1 = -1e30f, lS0 = 0.f, lS1 = 0.f;

    for (int jt = 0; jt <= lastj; jt++) {
        const int s = jt & 1;
        if (jt == lastj) asm volatile("cp.async.wait_group 0;" ::: "memory");
        else             asm volatile("cp.async.wait_group 1;" ::: "memory");
        __syncthreads();
        const uint32_t kh = sb + QSM + s * KVSM;
        const uint32_t kl = kh + 64 * STR;
        const uint32_t vh = kh + 128 * STR;
        const uint32_t vl = kh + 192 * STR;

        float accS[8][4];
#pragma unroll
        for (int i = 0; i < 8; i++)
#pragma unroll
            for (int j = 0; j < 4; j++) accS[i][j] = 0.f;
#pragma unroll
        for (int kc = 0; kc < 8; kc++) {
            uint32_t aQh[4], aQl[4];
            ldmx4(aQh, sQh + aAB + kc * 32);
            ldmx4(aQl, sQl + aAB + kc * 32);
#pragma unroll
            for (int ntp = 0; ntp < 4; ntp++) {
                uint32_t bKh[4], bKl[4];
                ldmx4(bKh, kh + bAB + ntp * (16 * STR) + kc * 32);
                ldmx4(bKl, kl + bAB + ntp * (16 * STR) + kc * 32);
                mma16816(accS[2 * ntp],     aQh, bKh[0], bKh[1]);
                mma16816(accS[2 * ntp + 1], aQh, bKh[2], bKh[3]);
                mma16816(accS[2 * ntp],     aQl, bKh[0], bKh[1]);
                mma16816(accS[2 * ntp + 1], aQl, bKh[2], bKh[3]);
                mma16816(accS[2 * ntp],     aQh, bKl[0], bKl[1]);
                mma16816(accS[2 * ntp + 1], aQh, bKl[2], bKl[3]);
            }
        }

        const int j0 = jt * 64;
        const int qi0 = t0 + m0 + g;
        const int qi1 = qi0 + 8;
        float mx0 = -1e30f, mx1 = -1e30f;
#pragma unroll
        for (int nt = 0; nt < 8; nt++) {
            const int kj = j0 + nt * 8 + qd * 2;
            float s0 = accS[nt][0] * scl + slope * (float)(kj - qi0);
            float s1 = accS[nt][1] * scl + slope * (float)(kj + 1 - qi0);
            float s2 = accS[nt][2] * scl + slope * (float)(kj - qi1);
            float s3 = accS[nt][3] * scl + slope * (float)(kj + 1 - qi1);
            if (kj > qi0)     s0 = -1e30f;
            if (kj + 1 > qi0) s1 = -1e30f;
            if (kj > qi1)     s2 = -1e30f;
            if (kj + 1 > qi1) s3 = -1e30f;
            accS[nt][0] = s0; accS[nt][1] = s1; accS[nt][2] = s2; accS[nt][3] = s3;
            mx0 = fmaxf(mx0, fmaxf(s0, s1));
            mx1 = fmaxf(mx1, fmaxf(s2, s3));
        }
        mx0 = fmaxf(mx0, __shfl_xor_sync(0xffffffffu, mx0, 1));
        mx0 = fmaxf(mx0, __shfl_xor_sync(0xffffffffu, mx0, 2));
        mx1 = fmaxf(mx1, __shfl_xor_sync(0xffffffffu, mx1, 1));
        mx1 = fmaxf(mx1, __shfl_xor_sync(0xffffffffu, mx1, 2));
        const float mN0 = fmaxf(mS0, mx0), mN1 = fmaxf(mS1, mx1);
        const float sc0 = __expf(mS0 - mN0), sc1 = __expf(mS1 - mN1);
        float sum0 = 0.f, sum1 = 0.f;
#pragma unroll
        for (int nt = 0; nt < 8; nt++) {
            accS[nt][0] = __expf(accS[nt][0] - mN0);
            accS[nt][1] = __expf(accS[nt][1] - mN0);
            accS[nt][2] = __expf(accS[nt][2] - mN1);
            accS[nt][3] = __expf(accS[nt][3] - mN1);
            sum0 += accS[nt][0] + accS[nt][1];
            sum1 += accS[nt][2] + accS[nt][3];
        }
        sum0 += __shfl_xor_sync(0xffffffffu, sum0, 1);
        sum0 += __shfl_xor_sync(0xffffffffu, sum0, 2);
        sum1 += __shfl_xor_sync(0xffffffffu, sum1, 1);
        sum1 += __shfl_xor_sync(0xffffffffu, sum1, 2);
        lS0 = lS0 * sc0 + sum0;
        lS1 = lS1 * sc1 + sum1;
        mS0 = mN0; mS1 = mN1;
#pragma unroll
        for (int nt = 0; nt < 16; nt++) {
            accO[nt][0] *= sc0; accO[nt][1] *= sc0;
            accO[nt][2] *= sc1; accO[nt][3] *= sc1;
        }

        uint32_t aPh[4][4], aPl[4][4];
#pragma unroll
        for (int kc = 0; kc < 4; kc++) {
#pragma unroll
            for (int e = 0; e < 4; e++) {
                const int nt = 2 * kc + (e >> 1);
                const int b0 = (e & 1) * 2;
                const float p0 = accS[nt][b0], p1 = accS[nt][b0 + 1];
                const __nv_bfloat16 h0 = __float2bfloat16_rn(p0);
                const __nv_bfloat16 h1 = __float2bfloat16_rn(p1);
                __nv_bfloat162 hh = __halves2bfloat162(h0, h1);
                memcpy(&aPh[kc][e], &hh, 4);
                aPl[kc][e] = pk_bf2(p0 - __bfloat162float(h0),
                                    p1 - __bfloat162float(h1));
            }
        }

#pragma unroll
        for (int ntp = 0; ntp < 8; ntp++) {
#pragma unroll
            for (int kc = 0; kc < 4; kc++) {
                uint32_t bVh[4], bVl[4];
                ldmx4t(bVh, vh + vAB + kc * (16 * STR) + ntp * 32);
                ldmx4t(bVl, vl + vAB + kc * (16 * STR) + ntp * 32);
                mma16816(accO[2 * ntp],     aPh[kc], bVh[0], bVh[1]);
                mma16816(accO[2 * ntp + 1], aPh[kc], bVh[2], bVh[3]);
                mma16816(accO[2 * ntp],     aPl[kc], bVh[0], bVh[1]);
                mma16816(accO[2 * ntp + 1], aPl[kc], bVh[2], bVh[3]);
                mma16816(accO[2 * ntp],     aPh[kc], bVl[0], bVl[1]);
                mma16816(accO[2 * ntp + 1], aPh[kc], bVl[2], bVl[3]);
            }
        }
        __syncthreads();
        if (jt + 2 <= lastj) loadKV(jt + 2, s);
    }

    const float i0 = 1.f / lS0, i1 = 1.f / lS1;
    const size_t base0 = (size_t)(t0 + m0 + g) * DM + h * HD + qd * 2;
    const size_t base1 = base0 + (size_t)8 * DM;
#pragma unroll
    for (int nt = 0; nt < 16; nt++) {
        float a0 = accO[nt][0] * i0, a1 = accO[nt][1] * i0;
        float a2 = accO[nt][2] * i1, a3 = accO[nt][3] * i1;
        __nv_bfloat16 h0, h1, h2, h3, l0, l1, l2, l3;
        hilo(a0, h0, l0); hilo(a1, h1, l1);
        hilo(a2, h2, l2); hilo(a3, h3, l3);
        *(__nv_bfloat162*)(g_at_h + base0 + nt * 8) = __halves2bfloat162(h0, h1);
        *(__nv_bfloat162*)(g_at_l + base0 + nt * 8) = __halves2bfloat162(l0, l1);
        *(__nv_bfloat162*)(g_at_h + base1 + nt * 8) = __halves2bfloat162(h2, h3);
        *(__nv_bfloat162*)(g_at_l + base1 + nt * 8) = __halves2bfloat162(l2, l3);
    }
}

// ---------------- launch ------------------------------------------------------
extern "C" void kernel_launch(void* const* d_in, const int* in_sizes, int n_in,
                              void* d_out, int out_size)
{
    const float* hs   = (const float*)d_in[0];
    const float* Wqkv = (const float*)d_in[1];
    const float* qw   = (const float*)d_in[2];
    const float* qb   = (const float*)d_in[3];
    const float* kw   = (const float*)d_in[4];
    const float* kb   = (const float*)d_in[5];
    const float* outw = (const float*)d_in[6];
    const float* kc   = (const float*)d_in[7];
    const float* vc   = (const float*)d_in[8];
    const int*   cidx = (const int*)d_in[9];
    const int*   Sk   = (const int*)d_in[10];
    float* out = (float*)d_out;

    float *p_qkv;
    cudaGetSymbolAddress((void**)&p_qkv,  g_qkv);
    __nv_bfloat16 *hs_h, *hs_l, *w1_h, *w1_l, *ow_h, *ow_l, *at_h, *at_l;
    cudaGetSymbolAddress((void**)&hs_h, g_hs_h);
    cudaGetSymbolAddress((void**)&hs_l, g_hs_l);
    cudaGetSymbolAddress((void**)&w1_h, g_w1_h);
    cudaGetSymbolAddress((void**)&w1_l, g_w1_l);
    cudaGetSymbolAddress((void**)&ow_h, g_ow_h);
    cudaGetSymbolAddress((void**)&ow_l, g_ow_l);
    cudaGetSymbolAddress((void**)&at_h, g_at_h);
    cudaGetSymbolAddress((void**)&at_l, g_at_l);

    cudaFuncSetAttribute(gemm_mma, cudaFuncAttributeMaxDynamicSharedMemorySize,
                         GSM_BYTES);
    cudaFuncSetAttribute(attn_mma, cudaFuncAttributeMaxDynamicSharedMemorySize,
                         ATT_SMEM);

    // 0. bf16 hi/lo splits of GEMM operands (fused, 1 launch)
    const int n_hs = (TT * DM) / 4096;
    const int n_w1 = (int)(((size_t)DQKV * DM) / 4096);
    const int n_ow = (DM * DM) / 4096;
    split3_kernel<<<n_hs + n_w1 + n_ow, 256>>>(
        hs, hs_h, hs_l, Wqkv, w1_h, w1_l, outw, ow_h, ow_l, n_hs, n_w1);
    // 1. QKV projection + clip (persistent: 384 tiles on 148 CTAs)
    gemm_mma<<<148, 256, GSM_BYTES>>>(
        hs_h, hs_l, w1_h, w1_l, p_qkv, DQKV, 1, 384, DQKV / 128);
    // 2. fused LN(q)+LN(k)+Sk-mask+gather+blend+splits
    qkv_post<<<TT, 256>>>(kc, vc, cidx, Sk, qw, qb, kw, kb);
    // 3. attention
    attn_mma<<<dim3(TT / 128, NH), 256, ATT_SMEM>>>();
    // 4. output projection (128 tiles -> single wave)
    gemm_mma<<<128, 256, GSM_BYTES>>>(
        at_h, at_l, ow_h, ow_l, out, DM, 0, 128, DM / 128);
}